// round 17
// baseline (speedup 1.0000x reference)
#include <cuda_runtime.h>
#include <cuda_fp16.h>
#include <cstdint>

// Conv3x3(s1,p1) + PixelUnshuffle(2), warp-level mma.sync implicit GEMM, v6.
// x:(8,96,256,256)f32  W:(48,96,3,3)f32  out:(8,192,128,128)f32
// CTA: 32h x 32w tile = 2 subtiles of 16h x 32w (M=512). 256 threads, 8 warps;
// each warp: mt=4 m-tiles (64 rows) x nt=6 n-tiles (all 48 oc) -> 24 MMAs/tap
// from 7 ldsm.x4 (1.17 wavefronts/MMA, half of v5). Single-pass fp16.
// Double-buffered A smem, 1 syncthreads per chunk, LDG prefetch overlap.

#define IC  96
#define HH  256
#define WW  256
#define OCN 48

#define A_CELLS 612            // 18 x 34 (16h subtile + 2 halo)
#define A_STR   24             // halfwords per cell (16 ic + 8 pad) = 48 B
#define A_BYTESZ 29376         // 612*24*2 per buffer
#define W_STR   104            // halfwords per oc row (96 ic + 8 pad) = 208 B
#define W_BYTESZ 89856         // 9*48*104*2
#define OFF_W   (2 * A_BYTESZ) // two A buffers = 58752
#define SMEM_BYTES (OFF_W + W_BYTESZ)   // 148608

#define NTHREADS 256
#define NUNIT 1224             // 612 cells x 2 ic-blocks
#define NSLOT 5                // ceil(1224/256)

static __device__ __forceinline__ uint32_t smem_u32(const void* p) {
    uint32_t a;
    asm("{ .reg .u64 t; cvta.to.shared.u64 t, %1; cvt.u32.u64 %0, t; }" : "=r"(a) : "l"(p));
    return a;
}
static __device__ __forceinline__ void mma_f16(float* d, const uint32_t* a, const uint32_t* b) {
    asm volatile(
        "mma.sync.aligned.m16n8k16.row.col.f32.f16.f16.f32 "
        "{%0,%1,%2,%3}, {%4,%5,%6,%7}, {%8,%9}, {%0,%1,%2,%3};"
        : "+f"(d[0]), "+f"(d[1]), "+f"(d[2]), "+f"(d[3])
        : "r"(a[0]), "r"(a[1]), "r"(a[2]), "r"(a[3]), "r"(b[0]), "r"(b[1]));
}
static __device__ __forceinline__ void ldsm_x4(uint32_t* r, uint32_t addr) {
    asm volatile("ldmatrix.sync.aligned.m8n8.x4.shared.b16 {%0,%1,%2,%3}, [%4];"
                 : "=r"(r[0]), "=r"(r[1]), "=r"(r[2]), "=r"(r[3]) : "r"(addr));
}
static __device__ __forceinline__ unsigned short to_h(float v) {
    return __half_as_ushort(__float2half_rn(v));
}

__global__ void __launch_bounds__(NTHREADS, 1)
conv_unshuffle_mma6(const float* __restrict__ x,
                    const float* __restrict__ Wg,
                    float* __restrict__ out)
{
    extern __shared__ __align__(128) char sm[];
    const uint32_t smb = smem_u32(sm);
    unsigned short* wH = (unsigned short*)(sm + OFF_W);

    const int tid  = threadIdx.x;
    const int lane = tid & 31;
    const int wid  = tid >> 5;
    const int mbase = wid * 64;             // 8 warps x 64 rows = M 512

    const int w0  = blockIdx.x * 32;
    const int h0c = blockIdx.y * 32;
    const int b   = blockIdx.z;
    const long long x_b = (long long)b * IC * HH * WW;

    // ---- per-thread staging unit metadata: unit = (8-ic block, cell) ----
    int gOffU[NSLOT];       // icb*8*HW + hr*WW + win
    int pkU[NSLOT];         // hr | (validW<<8) | (unitValid<<9)
    uint32_t sAddrU[NSLOT]; // byte offset into A buffer
#pragma unroll
    for (int j = 0; j < NSLOT; ++j) {
        const int u  = tid + j * NTHREADS;
        const int uv = (u < NUNIT) ? 1 : 0;
        const int u2 = uv ? u : 0;
        const int icb = u2 / A_CELLS;
        const int cel = u2 - icb * A_CELLS;
        const int hr  = cel / 34;
        const int wc  = cel - hr * 34;
        const int win = w0 + wc - 1;
        const int vw  = ((unsigned)win < WW) ? 1 : 0;
        gOffU[j]  = icb * 8 * (HH * WW) + hr * WW + win;
        pkU[j]    = hr | (vw << 8) | (uv << 9);
        sAddrU[j] = (uint32_t)(cel * (A_STR * 2) + icb * 16);
    }

    // ---- per-lane ldmatrix bases ----
    const int lrow  = lane & 15;
    const int lkoff = (lane >> 4) * 16;
    uint32_t aB[4];
#pragma unroll
    for (int mt = 0; mt < 4; ++mt) {
        const int m  = mbase + mt * 16 + lrow;
        const int hl = m >> 5;
        const int wl = m & 31;
        aB[mt] = smb + (uint32_t)((hl * 34 + wl) * (A_STR * 2)) + lkoff;
    }
    uint32_t bB[3];
#pragma unroll
    for (int t = 0; t < 3; ++t)
        bB[t] = smb + OFF_W + (uint32_t)((t * 16 + lrow) * (W_STR * 2)) + lkoff;

    float v[NSLOT][8];
    auto LOADA = [&](int h0s, int ic0) {
        const long long base = x_b + (long long)ic0 * (HH * WW) + (long long)(h0s - 1) * WW;
#pragma unroll
        for (int j = 0; j < NSLOT; ++j) {
            const int hin = h0s - 1 + (pkU[j] & 255);
            const bool ok = (pkU[j] & 512) && (pkU[j] & 256) && ((unsigned)hin < HH);
#pragma unroll
            for (int e = 0; e < 8; ++e)
                v[j][e] = ok ? __ldg(&x[base + gOffU[j] + (long long)e * (HH * WW)]) : 0.0f;
        }
    };

    // prefetch A(subtile 0, chunk 0); LDGs fly during weight staging
    LOADA(h0c, 0);

    // ---- stage ALL weights once, coalesced LDG, scatter STS ----
    for (int idx = tid; idx < OCN * IC * 9; idx += NTHREADS) {
        const int oc  = idx / (IC * 9);
        const int r   = idx - oc * (IC * 9);
        const int ic  = r / 9;
        const int tap = r - ic * 9;
        wH[(tap * OCN + oc) * W_STR + ic] = to_h(Wg[idx]);
    }

    for (int sub = 0; sub < 2; ++sub) {
        const int h0s = h0c + sub * 16;
        float acc[4][6][4];
#pragma unroll
        for (int mt = 0; mt < 4; ++mt)
#pragma unroll
            for (int nt = 0; nt < 6; ++nt)
#pragma unroll
                for (int e = 0; e < 4; ++e) acc[mt][nt][e] = 0.0f;

#pragma unroll 1
        for (int ch = 0; ch < 6; ++ch) {
            const int it = sub * 6 + ch;
            const uint32_t bufoff = (uint32_t)((it & 1) * A_BYTESZ);

            // ---- stage this chunk (v -> smem buffer), STS.128 conflict-free ----
#pragma unroll
            for (int j = 0; j < NSLOT; ++j) {
                if (pkU[j] & 512) {
                    __half2 h0 = __floats2half2_rn(v[j][0], v[j][1]);
                    __half2 h1 = __floats2half2_rn(v[j][2], v[j][3]);
                    __half2 h2 = __floats2half2_rn(v[j][4], v[j][5]);
                    __half2 h3 = __floats2half2_rn(v[j][6], v[j][7]);
                    uint4 q;
                    q.x = *(uint32_t*)&h0;  q.y = *(uint32_t*)&h1;
                    q.z = *(uint32_t*)&h2;  q.w = *(uint32_t*)&h3;
                    *(uint4*)(sm + bufoff + sAddrU[j]) = q;
                }
            }
            __syncthreads();   // staging visible; prior chunk's MMAs (other buffer) done

            // issue next chunk's LDGs (in flight during MMA below)
            if (it < 11) {
                const int nsub = (ch < 5) ? sub : sub + 1;
                const int nch  = (ch < 5) ? ch + 1 : 0;
                LOADA(h0c + nsub * 16, nch * 16);
            }

            // ---- MMA over 9 taps: 7 ldsm.x4 -> 24 MMAs per tap ----
            const uint32_t icb = (uint32_t)(ch * 32);   // 16 ic * 2 B
#pragma unroll
            for (int tap = 0; tap < 9; ++tap) {
                const int dy = tap / 3;
                const int dx = tap - dy * 3;
                const uint32_t aoff = bufoff + (uint32_t)((dy * 34 + dx) * (A_STR * 2));
                const uint32_t woff = (uint32_t)(tap * (OCN * W_STR * 2)) + icb;

                uint32_t ah[4][4];
#pragma unroll
                for (int mt = 0; mt < 4; ++mt)
                    ldsm_x4(ah[mt], aB[mt] + aoff);

                uint32_t br[3][4];
#pragma unroll
                for (int t = 0; t < 3; ++t)
                    ldsm_x4(br[t], bB[t] + woff);
                // n-tile fragments: x4 at rows[16t..16t+16) -> tiles 2t, 2t+1
                uint32_t bf[6][2] = {
                    {br[0][0], br[0][2]}, {br[0][1], br[0][3]},
                    {br[1][0], br[1][2]}, {br[1][1], br[1][3]},
                    {br[2][0], br[2][2]}, {br[2][1], br[2][3]} };

#pragma unroll
                for (int mt = 0; mt < 4; ++mt)
#pragma unroll
                    for (int nt = 0; nt < 6; ++nt)
                        mma_f16(acc[mt][nt], ah[mt], bf[nt]);
            }
        }

        // ---- epilogue: fused PixelUnshuffle(2) scatter for this subtile ----
        const int r0 = lane >> 2;
        const int c0 = (lane & 3) * 2;
#pragma unroll
        for (int mt = 0; mt < 4; ++mt) {
#pragma unroll
            for (int pair = 0; pair < 2; ++pair) {
                const int m  = mbase + mt * 16 + r0 + pair * 8;
                const int hl = m >> 5;
                const int wl = m & 31;
                const int h  = h0s + hl;
                const int w  = w0 + wl;
                const int cb = (h & 1) * 2 + (w & 1);
                const long long pxbase =
                    (((long long)b * 192 + cb) * 128 + (h >> 1)) * 128 + (w >> 1);
#pragma unroll
                for (int nt = 0; nt < 6; ++nt) {
                    const int oc0 = nt * 8 + c0;
                    out[pxbase + (long long)(oc0    ) * 4 * 128 * 128] = acc[mt][nt][pair * 2 + 0];
                    out[pxbase + (long long)(oc0 + 1) * 4 * 128 * 128] = acc[mt][nt][pair * 2 + 1];
                }
            }
        }
    }
}

extern "C" void kernel_launch(void* const* d_in, const int* in_sizes, int n_in,
                              void* d_out, int out_size)
{
    const float* x  = (const float*)d_in[0];
    const float* Wg = (const float*)d_in[1];
    float* out = (float*)d_out;

    static int configured = 0;
    if (!configured) {
        cudaFuncSetAttribute(conv_unshuffle_mma6,
                             cudaFuncAttributeMaxDynamicSharedMemorySize, SMEM_BYTES);
        configured = 1;
    }

    dim3 grid(WW / 32, HH / 32, 8);   // (8, 8, 8) = 512 CTAs
    conv_unshuffle_mma6<<<grid, NTHREADS, SMEM_BYTES>>>(x, Wg, out);
}